// round 2
// baseline (speedup 1.0000x reference)
#include <cuda_runtime.h>
#include <math.h>

#define BB 4
#define SS 4096
#define DD 256
#define UU 64

#define ROWS_PER_BLK 16     // projection kernel
#define MT 64               // query tile
#define NT 64               // key tile
#define ST 68               // padded smem stride (floats); 68*4B = 272B, 16B-aligned

// Scratch for projected Q/K/V (no cudaMalloc allowed)
__device__ float g_q[BB * SS * UU];
__device__ float g_k[BB * SS * UU];
__device__ float g_v[BB * SS * UU];

// ---------------------------------------------------------------------------
// Fused QKV projection: out[row,u] = sum_d x[row,d]*W[d,u] + b[u]
// 16 rows per block, 192 threads = 3 matrices x 64 units.
// x tile in smem (broadcast reads), W columns streamed from L2 (coalesced).
// ---------------------------------------------------------------------------
__global__ __launch_bounds__(192) void proj_kernel(
    const float* __restrict__ x,
    const float* __restrict__ Wq, const float* __restrict__ bq,
    const float* __restrict__ Wk, const float* __restrict__ bk,
    const float* __restrict__ Wv, const float* __restrict__ bv)
{
    __shared__ float xs[ROWS_PER_BLK * DD];

    const int row0 = blockIdx.x * ROWS_PER_BLK;
    const float* xrow = x + (size_t)row0 * DD;

    // cooperative load: 16*256 floats = 1024 float4
    for (int i = threadIdx.x; i < ROWS_PER_BLK * DD / 4; i += blockDim.x) {
        ((float4*)xs)[i] = ((const float4*)xrow)[i];
    }
    __syncthreads();

    const int mat = threadIdx.x / UU;   // 0=Q 1=K 2=V
    const int u   = threadIdx.x % UU;
    const float* W    = (mat == 0) ? Wq : (mat == 1) ? Wk : Wv;
    const float* bias = (mat == 0) ? bq : (mat == 1) ? bk : bv;
    float*       out  = (mat == 0) ? g_q : (mat == 1) ? g_k : g_v;

    float acc[ROWS_PER_BLK];
    const float b0 = bias[u];
#pragma unroll
    for (int r = 0; r < ROWS_PER_BLK; r++) acc[r] = b0;

#pragma unroll 8
    for (int d = 0; d < DD; d++) {
        const float w = W[d * UU + u];          // coalesced across lanes, L2-resident
#pragma unroll
        for (int r = 0; r < ROWS_PER_BLK; r++)  // smem broadcast reads
            acc[r] = fmaf(xs[r * DD + d], w, acc[r]);
    }

#pragma unroll
    for (int r = 0; r < ROWS_PER_BLK; r++)
        out[(size_t)(row0 + r) * UU + u] = acc[r];
}

// ---------------------------------------------------------------------------
// Flash attention, fp32 SIMT.
// Block: 256 threads = 16(tx) x 16(ty). Block handles 64 query rows of one
// batch. Per thread: 4 rows (m = 4*ty+i) x 4 cols. Online softmax state
// (m_i, l_i) is per-row and uniform across tx after shuffle reduction, so it
// lives entirely in registers; the PV stage uses the same row ownership.
// smem (dynamic): Qs[64][ST] (natural, pre-scaled), Kt[64(u)][ST(n)]
// (transposed, float4-friendly), Vs[64][ST] (natural), Ps[64][ST] (natural).
// ---------------------------------------------------------------------------
__global__ __launch_bounds__(256) void attn_kernel(float* __restrict__ out)
{
    extern __shared__ float smem[];
    float* Qs = smem;                 // [MT][ST]  q, scaled by 1/sqrt(U)
    float* Kt = Qs + MT * ST;         // [UU][ST]  K transposed: Kt[u][n]
    float* Vs = Kt + UU * ST;         // [NT][ST]  Vs[n][u]
    float* Ps = Vs + NT * ST;         // [MT][ST]  Ps[m][n]

    const int b  = blockIdx.x / (SS / MT);
    const int mt = blockIdx.x % (SS / MT);
    const int tid = threadIdx.x;
    const int tx = tid % 16;
    const int ty = tid / 16;

    const float* qg = g_q + ((size_t)b * SS + (size_t)mt * MT) * UU;
    const float* kg = g_k + (size_t)b * SS * UU;
    const float* vg = g_v + (size_t)b * SS * UU;

    // Load Q tile (natural layout), fold in 1/sqrt(64) = 0.125
    for (int i = tid; i < MT * UU / 4; i += 256) {
        const int m = i / (UU / 4);
        const int u4 = (i % (UU / 4)) * 4;
        float4 q4 = *(const float4*)(qg + m * UU + u4);
        q4.x *= 0.125f; q4.y *= 0.125f; q4.z *= 0.125f; q4.w *= 0.125f;
        *(float4*)&Qs[m * ST + u4] = q4;
    }

    float m_i[4], l_i[4], o[4][4];
#pragma unroll
    for (int i = 0; i < 4; i++) {
        m_i[i] = -1e30f;
        l_i[i] = 0.f;
#pragma unroll
        for (int j = 0; j < 4; j++) o[i][j] = 0.f;
    }

    for (int nt = 0; nt < SS / NT; nt++) {
        __syncthreads();  // previous iteration done reading Kt/Vs (and Qs visible on iter 0 after next sync)

        // --- load K tile TRANSPOSED: thread mapping u-fast so global reads
        //     stay coalesced and the smem store is a single float4 ---
        {
            const float* kp = kg + (size_t)nt * NT * UU;
            for (int i = tid; i < UU * (NT / 4); i += 256) {
                const int u  = i % UU;
                const int n4 = (i / UU) * 4;
                float4 kv;
                kv.x = kp[(n4 + 0) * UU + u];
                kv.y = kp[(n4 + 1) * UU + u];
                kv.z = kp[(n4 + 2) * UU + u];
                kv.w = kp[(n4 + 3) * UU + u];
                *(float4*)&Kt[u * ST + n4] = kv;
            }
            // V tile natural layout
            const float* vp = vg + (size_t)nt * NT * UU;
            for (int i = tid; i < NT * UU / 4; i += 256) {
                const int n = i / (UU / 4);
                const int u4 = (i % (UU / 4)) * 4;
                *(float4*)&Vs[n * ST + u4] = *(const float4*)(vp + n * UU + u4);
            }
        }
        __syncthreads();

        // --- S = Q K^T : s[i][j] for rows 4ty+i, cols 4tx+j ---
        float s[4][4];
#pragma unroll
        for (int i = 0; i < 4; i++)
#pragma unroll
            for (int j = 0; j < 4; j++) s[i][j] = 0.f;

#pragma unroll 4
        for (int u = 0; u < UU; u++) {
            float a[4];
#pragma unroll
            for (int i = 0; i < 4; i++)
                a[i] = Qs[(4 * ty + i) * ST + u];        // broadcast
            const float4 k4 = *(const float4*)&Kt[u * ST + 4 * tx];  // conflict-free
            const float kb[4] = {k4.x, k4.y, k4.z, k4.w};
#pragma unroll
            for (int i = 0; i < 4; i++)
#pragma unroll
                for (int j = 0; j < 4; j++)
                    s[i][j] = fmaf(a[i], kb[j], s[i][j]);
        }

        // --- online softmax (per-row state in registers, reduce across tx) ---
#pragma unroll
        for (int i = 0; i < 4; i++) {
            float rm = fmaxf(fmaxf(s[i][0], s[i][1]), fmaxf(s[i][2], s[i][3]));
#pragma unroll
            for (int off = 1; off < 16; off <<= 1)
                rm = fmaxf(rm, __shfl_xor_sync(0xffffffffu, rm, off));
            const float mnew = fmaxf(m_i[i], rm);
            const float corr = __expf(m_i[i] - mnew);
            m_i[i] = mnew;
            float rs = 0.f;
#pragma unroll
            for (int j = 0; j < 4; j++) {
                s[i][j] = __expf(s[i][j] - mnew);
                rs += s[i][j];
            }
#pragma unroll
            for (int off = 1; off < 16; off <<= 1)
                rs += __shfl_xor_sync(0xffffffffu, rs, off);
            l_i[i] = l_i[i] * corr + rs;
#pragma unroll
            for (int j = 0; j < 4; j++) o[i][j] *= corr;
        }

        // --- stash P in natural [m][n] layout (float4, conflict-free) ---
#pragma unroll
        for (int i = 0; i < 4; i++) {
            float4 p4; p4.x = s[i][0]; p4.y = s[i][1]; p4.z = s[i][2]; p4.w = s[i][3];
            *(float4*)&Ps[(4 * ty + i) * ST + 4 * tx] = p4;
        }
        __syncthreads();

        // --- O += P V : rows 4ty+i (broadcast reads of P), cols 4tx+j ---
#pragma unroll 4
        for (int n = 0; n < NT; n++) {
            float p[4];
#pragma unroll
            for (int i = 0; i < 4; i++)
                p[i] = Ps[(4 * ty + i) * ST + n];        // broadcast
            const float4 v4 = *(const float4*)&Vs[n * ST + 4 * tx];  // conflict-free
            const float vb[4] = {v4.x, v4.y, v4.z, v4.w};
#pragma unroll
            for (int i = 0; i < 4; i++)
#pragma unroll
                for (int j = 0; j < 4; j++)
                    o[i][j] = fmaf(p[i], vb[j], o[i][j]);
        }
    }

    // --- epilogue: normalize and write out[B,S,U] ---
    float* op = out + ((size_t)b * SS + (size_t)mt * MT) * UU;
#pragma unroll
    for (int i = 0; i < 4; i++) {
        const float inv = 1.f / l_i[i];
        const int m = 4 * ty + i;
        float4 r;
        r.x = o[i][0] * inv; r.y = o[i][1] * inv;
        r.z = o[i][2] * inv; r.w = o[i][3] * inv;
        *(float4*)(op + m * UU + 4 * tx) = r;
    }
}

// ---------------------------------------------------------------------------
extern "C" void kernel_launch(void* const* d_in, const int* in_sizes, int n_in,
                              void* d_out, int out_size)
{
    const float* x  = (const float*)d_in[0];
    const float* Wq = (const float*)d_in[1];
    const float* bq = (const float*)d_in[2];
    const float* Wk = (const float*)d_in[3];
    const float* bk = (const float*)d_in[4];
    const float* Wv = (const float*)d_in[5];
    const float* bv = (const float*)d_in[6];
    float* out = (float*)d_out;

    proj_kernel<<<(BB * SS) / ROWS_PER_BLK, 192>>>(x, Wq, bq, Wk, bk, Wv, bv);

    const int smem_bytes = (MT + UU + NT + MT) * ST * (int)sizeof(float); // 69,632 B
    static bool attr_set = false;
    // (idempotent; runs outside capture semantics — not a stream op)
    cudaFuncSetAttribute(attn_kernel, cudaFuncAttributeMaxDynamicSharedMemorySize,
                         smem_bytes);
    (void)attr_set;
    attn_kernel<<<BB * (SS / MT), 256, smem_bytes>>>(out);
}